// round 3
// baseline (speedup 1.0000x reference)
#include <cuda_runtime.h>
#include <cuda_bf16.h>
#include <cstdint>

// Problem dims (fixed by the reference): M = B*S = 16384, N = H = 512, K = IN = 512
#define KDIM 512
#define NDIM 512
#define BM 128
#define BN 128
#define BK 32
#define NKT (KDIM / BK) /* 16 */
#define ROWB 80          /* smem row stride in bytes: 32 bf16 (64B) + 16B pad -> conflict-free ldmatrix */
#define ABYTES (BM * ROWB)
#define BUFBYTES (2 * ABYTES)

__device__ __forceinline__ uint32_t smem_u32(const void* p) {
    return (uint32_t)__cvta_generic_to_shared(p);
}

// Hodgkin-Huxley + adaptive-LIF epilogue (first-call semantics: all states at init)
__device__ __forceinline__ void snn_epilogue(float V, float gNa, float gK, float gL,
                                             float& spike, float& v_rs, float& w_new) {
    const float am = 0.1f * (V + 40.0f) / (1.0f - __expf(-(V + 40.0f) * 0.1f));
    const float bm = 4.0f * __expf(-(V + 65.0f) * (1.0f / 18.0f));
    const float ah = 0.07f * __expf(-(V + 65.0f) * 0.05f);
    const float bh = 1.0f / (1.0f + __expf(-(V + 35.0f) * 0.1f));
    const float an = 0.01f * (V + 55.0f) / (1.0f - __expf(-(V + 55.0f) * 0.1f));
    const float bn = 0.125f * __expf(-(V + 65.0f) * 0.0125f);
    // one Euler step from gate init values m0=0.05, h0=0.6, n0=0.32, dt=0.1
    const float m = 0.05f + 0.1f * (am * 0.95f - bm * 0.05f);
    const float h = 0.60f + 0.1f * (ah * 0.40f - bh * 0.60f);
    const float n = 0.32f + 0.1f * (an * 0.68f - bn * 0.32f);
    const float n2 = n * n;
    const float I_ion = gNa * m * m * m * h * (V - 50.0f)
                      + gK * n2 * n2 * (V + 77.0f)
                      + gL * (V + 54.4f);
    const float I_in = I_ion + V;                 // psp = V
    const float v_new = -65.0f + I_in * 0.005f;   // dt/tau_m
    const float s = (v_new >= -50.0f) ? 1.0f : 0.0f;
    spike = s;
    w_new = (0.5f * (v_new + 65.0f) + 0.1f * s) * 0.001f;  // dt/tau_adapt
    v_rs = (s > 0.5f) ? -65.0f : v_new;
}

__global__ __launch_bounds__(256) void CSnT_snn_kernel(
    const float* __restrict__ x, const float* __restrict__ W,
    const float* __restrict__ gNa_p, const float* __restrict__ gK_p,
    const float* __restrict__ gL_p,
    float* __restrict__ out, int M) {
    __shared__ __align__(16) unsigned char smem[2 * BUFBYTES];  // 40 KB, double buffered A+B

    const int tid = threadIdx.x;
    const int lane = tid & 31;
    const int warp = tid >> 5;
    const int wm = warp & 3;   // 4 warps along M  -> 32 rows each
    const int wn = warp >> 2;  // 2 warps along N  -> 64 cols each
    const int m0 = blockIdx.y * BM;
    const int n0 = blockIdx.x * BN;

    // ---- global load mapping: 256 threads load 128x32 fp32 tiles for A and B ----
    const int c4 = tid & 7;   // float4 column within a 32-float row
    const int r0 = tid >> 3;  // 0..31, 4 passes of 32 rows
    const float* gA = x + (size_t)(m0 + r0) * KDIM + c4 * 4;
    const float* gB = W + (size_t)(n0 + r0) * KDIM + c4 * 4;

    float4 ra[4], rb[4];

    auto gload = [&](int kt) {
        const float* a = gA + kt * BK;
        const float* b = gB + kt * BK;
#pragma unroll
        for (int i = 0; i < 4; i++) {
            ra[i] = *(const float4*)(a + (size_t)i * 32 * KDIM);
            rb[i] = *(const float4*)(b + (size_t)i * 32 * KDIM);
        }
    };

    auto sstore = [&](int buf) {
        unsigned char* As = smem + buf * BUFBYTES;
        unsigned char* Bs = As + ABYTES;
#pragma unroll
        for (int i = 0; i < 4; i++) {
            const int row = r0 + 32 * i;
            __nv_bfloat162 p0 = __floats2bfloat162_rn(ra[i].x, ra[i].y);
            __nv_bfloat162 p1 = __floats2bfloat162_rn(ra[i].z, ra[i].w);
            uint2 va;
            va.x = *(uint32_t*)&p0;
            va.y = *(uint32_t*)&p1;
            *(uint2*)(As + row * ROWB + c4 * 8) = va;
            __nv_bfloat162 q0 = __floats2bfloat162_rn(rb[i].x, rb[i].y);
            __nv_bfloat162 q1 = __floats2bfloat162_rn(rb[i].z, rb[i].w);
            uint2 vb;
            vb.x = *(uint32_t*)&q0;
            vb.y = *(uint32_t*)&q1;
            *(uint2*)(Bs + row * ROWB + c4 * 8) = vb;
        }
    };

    float acc[2][8][4];
#pragma unroll
    for (int mt = 0; mt < 2; mt++)
#pragma unroll
        for (int nt = 0; nt < 8; nt++)
#pragma unroll
            for (int e = 0; e < 4; e++) acc[mt][nt][e] = 0.0f;

    gload(0);
    sstore(0);
    __syncthreads();

    for (int kt = 0; kt < NKT; kt++) {
        const int cur = kt & 1;
        if (kt + 1 < NKT) gload(kt + 1);

        unsigned char* As = smem + cur * BUFBYTES;
        unsigned char* Bs = As + ABYTES;

#pragma unroll
        for (int ks = 0; ks < 2; ks++) {
            uint32_t afr[2][4];
            uint32_t bfr[8][2];
#pragma unroll
            for (int mt = 0; mt < 2; mt++) {
                const int row = wm * 32 + mt * 16 + (lane & 15);
                const uint32_t addr =
                    smem_u32(As + row * ROWB + ks * 32 + ((lane >> 4) << 4));
                asm volatile(
                    "ldmatrix.sync.aligned.m8n8.x4.shared.b16 {%0,%1,%2,%3}, [%4];"
                    : "=r"(afr[mt][0]), "=r"(afr[mt][1]), "=r"(afr[mt][2]),
                      "=r"(afr[mt][3])
                    : "r"(addr));
            }
#pragma unroll
            for (int nt = 0; nt < 8; nt++) {
                const int i = lane & 15;
                const int row = wn * 64 + nt * 8 + (i & 7);
                const uint32_t addr =
                    smem_u32(Bs + row * ROWB + ks * 32 + ((i >> 3) << 4));
                asm volatile(
                    "ldmatrix.sync.aligned.m8n8.x2.shared.b16 {%0,%1}, [%2];"
                    : "=r"(bfr[nt][0]), "=r"(bfr[nt][1])
                    : "r"(addr));
            }
#pragma unroll
            for (int mt = 0; mt < 2; mt++)
#pragma unroll
                for (int nt = 0; nt < 8; nt++) {
                    asm volatile(
                        "mma.sync.aligned.m16n8k16.row.col.f32.bf16.bf16.f32 "
                        "{%0,%1,%2,%3}, {%4,%5,%6,%7}, {%8,%9}, {%0,%1,%2,%3};"
                        : "+f"(acc[mt][nt][0]), "+f"(acc[mt][nt][1]),
                          "+f"(acc[mt][nt][2]), "+f"(acc[mt][nt][3])
                        : "r"(afr[mt][0]), "r"(afr[mt][1]), "r"(afr[mt][2]),
                          "r"(afr[mt][3]), "r"(bfr[nt][0]), "r"(bfr[nt][1]));
                }
        }
        if (kt + 1 < NKT) {
            sstore((kt + 1) & 1);
            __syncthreads();
        }
    }

    // ---- fused epilogue + stores ----
    const float gNa = *gNa_p;
    const float gK = *gK_p;
    const float gL = *gL_p;
    const size_t MN = (size_t)M * NDIM;
    float* sp_out = out;
    float* vr_out = out + MN;
    float* wn_out = out + 2 * MN;

    const int rbase = m0 + wm * 32 + (lane >> 2);
    const int cbase = n0 + wn * 64 + (lane & 3) * 2;

#pragma unroll
    for (int mt = 0; mt < 2; mt++) {
#pragma unroll
        for (int half = 0; half < 2; half++) {
            const int row = rbase + mt * 16 + half * 8;
#pragma unroll
            for (int nt = 0; nt < 8; nt++) {
                const int col = cbase + nt * 8;
                const float V0 = acc[mt][nt][half * 2 + 0];
                const float V1 = acc[mt][nt][half * 2 + 1];
                float s0, v0, w0, s1, v1, w1;
                snn_epilogue(V0, gNa, gK, gL, s0, v0, w0);
                snn_epilogue(V1, gNa, gK, gL, s1, v1, w1);
                const size_t idx = (size_t)row * NDIM + col;
                float2 t;
                t.x = s0; t.y = s1;
                *(float2*)(sp_out + idx) = t;
                t.x = v0; t.y = v1;
                *(float2*)(vr_out + idx) = t;
                t.x = w0; t.y = w1;
                *(float2*)(wn_out + idx) = t;
            }
        }
    }
}

extern "C" void kernel_launch(void* const* d_in, const int* in_sizes, int n_in,
                              void* d_out, int out_size) {
    const float* x = (const float*)d_in[0];
    const float* W = (const float*)d_in[1];
    const float* gNa = (const float*)d_in[2];
    const float* gK = (const float*)d_in[3];
    const float* gL = (const float*)d_in[4];
    float* out = (float*)d_out;

    const int M = in_sizes[0] / KDIM;  // 16384
    dim3 grid(NDIM / BN, M / BM);      // (4, 128)
    CSnT_snn_kernel<<<grid, 256>>>(x, W, gNa, gK, gL, out, M);
}

// round 4
// speedup vs baseline: 1.2195x; 1.2195x over previous
#include <cuda_runtime.h>
#include <cuda_bf16.h>
#include <cstdint>

// Problem dims (fixed): M = B*S = 16384, N = H = 512, K = IN = 512
#define KDIM 512
#define NDIM 512
#define MDIM 16384
#define BM 128
#define BN 128
#define BK 32
#define NKT (KDIM / BK) /* 16 */
#define STAGES 4
#define ROWB 80 /* 32 bf16 (64B) + 16B pad -> conflict-free ldmatrix, 16B-aligned cp.async */
#define OPBYTES (BM * ROWB)        /* 10240 per operand per stage */
#define STAGE_BYTES (2 * OPBYTES)  /* 20480 */
#define SMEM_BYTES (STAGES * STAGE_BYTES) /* 81920 */

// bf16 scratch (device globals: allocation-free)
__device__ __align__(16) __nv_bfloat16 g_xb[(size_t)MDIM * KDIM];
__device__ __align__(16) __nv_bfloat16 g_wb[(size_t)NDIM * KDIM];

__device__ __forceinline__ uint32_t smem_u32(const void* p) {
    return (uint32_t)__cvta_generic_to_shared(p);
}

__device__ __forceinline__ void cp_async16(uint32_t dst, const void* src) {
    asm volatile("cp.async.cg.shared.global [%0], [%1], 16;\n" ::"r"(dst), "l"(src));
}

// ---------------- fp32 -> bf16 pre-convert ----------------
__global__ __launch_bounds__(256) void CSnT_cvt_kernel(const float* __restrict__ x,
                                                       const float* __restrict__ W) {
    const int nx8 = (MDIM * KDIM) / 8;
    const int nw8 = (NDIM * KDIM) / 8;
    const int total = nx8 + nw8;
    for (int i = blockIdx.x * blockDim.x + threadIdx.x; i < total;
         i += gridDim.x * blockDim.x) {
        const float4* src;
        __nv_bfloat16* dst;
        int j;
        if (i < nx8) {
            src = (const float4*)x;
            dst = g_xb;
            j = i;
        } else {
            src = (const float4*)W;
            dst = g_wb;
            j = i - nx8;
        }
        float4 a = src[2 * j];
        float4 b = src[2 * j + 1];
        uint4 o;
        __nv_bfloat162 p;
        p = __floats2bfloat162_rn(a.x, a.y); o.x = *(uint32_t*)&p;
        p = __floats2bfloat162_rn(a.z, a.w); o.y = *(uint32_t*)&p;
        p = __floats2bfloat162_rn(b.x, b.y); o.z = *(uint32_t*)&p;
        p = __floats2bfloat162_rn(b.z, b.w); o.w = *(uint32_t*)&p;
        *(uint4*)(dst + (size_t)8 * j) = o;
    }
}

// ---------------- HH + adaptive-LIF epilogue (6 MUFU instead of 9) ----------------
__device__ __forceinline__ void snn_epilogue(float V, float gNa, float gK, float gL,
                                             float& spike, float& v_rs, float& w_new) {
    // P = exp(-(V+55)/10); exp(-(V+40)/10)=P*e^1.5; exp(-(V+35)/10)=P*e^2
    const float P = __expf(-(V + 55.0f) * 0.1f);
    // E = exp(-(V+65)/80); exp(-(V+65)/20)=E^4
    const float E = __expf(-(V + 65.0f) * 0.0125f);
    const float bm = 4.0f * __expf(-(V + 65.0f) * (1.0f / 18.0f));

    const float am = 0.1f * (V + 40.0f) * __fdividef(1.0f, 1.0f - P * 4.48168907f);
    const float an = 0.01f * (V + 55.0f) * __fdividef(1.0f, 1.0f - P);
    const float bh = __fdividef(1.0f, 1.0f + P * 7.38905610f);
    const float E2 = E * E;
    const float ah = 0.07f * (E2 * E2);
    const float bn = 0.125f * E;

    const float m = 0.05f + 0.1f * (am * 0.95f - bm * 0.05f);
    const float h = 0.60f + 0.1f * (ah * 0.40f - bh * 0.60f);
    const float n = 0.32f + 0.1f * (an * 0.68f - bn * 0.32f);
    const float n2 = n * n;
    const float I_ion = gNa * m * m * m * h * (V - 50.0f)
                      + gK * n2 * n2 * (V + 77.0f)
                      + gL * (V + 54.4f);
    const float I_in = I_ion + V;                // psp = V
    const float v_new = -65.0f + I_in * 0.005f;  // dt/tau_m
    const float s = (v_new >= -50.0f) ? 1.0f : 0.0f;
    spike = s;
    w_new = (0.5f * (v_new + 65.0f) + 0.1f * s) * 0.001f;  // dt/tau_adapt
    v_rs = (s > 0.5f) ? -65.0f : v_new;
}

// ---------------- GEMM (cp.async 4-stage) + fused epilogue ----------------
__global__ __launch_bounds__(256) void CSnT_snn_kernel(
    const float* __restrict__ gNa_p, const float* __restrict__ gK_p,
    const float* __restrict__ gL_p, float* __restrict__ out, int M) {
    extern __shared__ __align__(16) unsigned char smem[];

    const int tid = threadIdx.x;
    const int lane = tid & 31;
    const int warp = tid >> 5;
    const int wm = warp & 3;   // 4 warps along M -> 32 rows each
    const int wn = warp >> 2;  // 2 warps along N -> 64 cols each
    const int m0 = blockIdx.y * BM;
    const int n0 = blockIdx.x * BN;

    // cp.async mapping: 512 chunks (16B) per operand per stage; 2 per thread each
    const int crow = tid >> 2;   // 0..63 (+64 on second pass)
    const int cc = tid & 3;      // 16B chunk within 64B row

    auto issue = [&](int kt) {
        const int stage = kt & (STAGES - 1);
        unsigned char* As = smem + stage * STAGE_BYTES;
        unsigned char* Bs = As + OPBYTES;
#pragma unroll
        for (int p = 0; p < 2; p++) {
            const int row = crow + p * 64;
            const __nv_bfloat16* ga = g_xb + (size_t)(m0 + row) * KDIM + kt * BK + cc * 8;
            cp_async16(smem_u32(As + row * ROWB + cc * 16), ga);
            const __nv_bfloat16* gb = g_wb + (size_t)(n0 + row) * KDIM + kt * BK + cc * 8;
            cp_async16(smem_u32(Bs + row * ROWB + cc * 16), gb);
        }
        asm volatile("cp.async.commit_group;\n");
    };

    float acc[2][8][4];
#pragma unroll
    for (int mt = 0; mt < 2; mt++)
#pragma unroll
        for (int nt = 0; nt < 8; nt++)
#pragma unroll
            for (int e = 0; e < 4; e++) acc[mt][nt][e] = 0.0f;

    // prologue: stages 0..2 in flight
#pragma unroll
    for (int kt = 0; kt < STAGES - 1; kt++) issue(kt);

    for (int kt = 0; kt < NKT; kt++) {
        asm volatile("cp.async.wait_group %0;\n" ::"n"(STAGES - 2));
        __syncthreads();
        if (kt + STAGES - 1 < NKT) issue(kt + STAGES - 1);

        unsigned char* As = smem + (kt & (STAGES - 1)) * STAGE_BYTES;
        unsigned char* Bs = As + OPBYTES;

#pragma unroll
        for (int ks = 0; ks < 2; ks++) {
            uint32_t afr[2][4];
            uint32_t bfr[8][2];
#pragma unroll
            for (int mt = 0; mt < 2; mt++) {
                const int row = wm * 32 + mt * 16 + (lane & 15);
                const uint32_t addr =
                    smem_u32(As + row * ROWB + ks * 32 + ((lane >> 4) << 4));
                asm volatile(
                    "ldmatrix.sync.aligned.m8n8.x4.shared.b16 {%0,%1,%2,%3}, [%4];"
                    : "=r"(afr[mt][0]), "=r"(afr[mt][1]), "=r"(afr[mt][2]),
                      "=r"(afr[mt][3])
                    : "r"(addr));
            }
            // B: x4 ldmatrix loads two nt fragments at once
#pragma unroll
            for (int p = 0; p < 4; p++) {
                const int idx16 = lane & 15;
                const int grp = lane >> 4;
                const int row = wn * 64 + p * 16 + grp * 8 + (idx16 & 7);
                const uint32_t addr =
                    smem_u32(Bs + row * ROWB + ks * 32 + ((idx16 >> 3) << 4));
                asm volatile(
                    "ldmatrix.sync.aligned.m8n8.x4.shared.b16 {%0,%1,%2,%3}, [%4];"
                    : "=r"(bfr[2 * p][0]), "=r"(bfr[2 * p][1]),
                      "=r"(bfr[2 * p + 1][0]), "=r"(bfr[2 * p + 1][1])
                    : "r"(addr));
            }
#pragma unroll
            for (int mt = 0; mt < 2; mt++)
#pragma unroll
                for (int nt = 0; nt < 8; nt++) {
                    asm volatile(
                        "mma.sync.aligned.m16n8k16.row.col.f32.bf16.bf16.f32 "
                        "{%0,%1,%2,%3}, {%4,%5,%6,%7}, {%8,%9}, {%0,%1,%2,%3};"
                        : "+f"(acc[mt][nt][0]), "+f"(acc[mt][nt][1]),
                          "+f"(acc[mt][nt][2]), "+f"(acc[mt][nt][3])
                        : "r"(afr[mt][0]), "r"(afr[mt][1]), "r"(afr[mt][2]),
                          "r"(afr[mt][3]), "r"(bfr[nt][0]), "r"(bfr[nt][1]));
                }
        }
    }

    // ---- fused epilogue + stores ----
    const float gNa = *gNa_p;
    const float gK = *gK_p;
    const float gL = *gL_p;
    const size_t MN = (size_t)M * NDIM;
    float* sp_out = out;
    float* vr_out = out + MN;
    float* wn_out = out + 2 * MN;

    const int rbase = m0 + wm * 32 + (lane >> 2);
    const int cbase = n0 + wn * 64 + (lane & 3) * 2;

#pragma unroll
    for (int mt = 0; mt < 2; mt++) {
#pragma unroll
        for (int half = 0; half < 2; half++) {
            const int row = rbase + mt * 16 + half * 8;
#pragma unroll
            for (int nt = 0; nt < 8; nt++) {
                const int col = cbase + nt * 8;
                const float V0 = acc[mt][nt][half * 2 + 0];
                const float V1 = acc[mt][nt][half * 2 + 1];
                float s0, v0, w0, s1, v1, w1;
                snn_epilogue(V0, gNa, gK, gL, s0, v0, w0);
                snn_epilogue(V1, gNa, gK, gL, s1, v1, w1);
                const size_t idx = (size_t)row * NDIM + col;
                float2 t;
                t.x = s0; t.y = s1;
                *(float2*)(sp_out + idx) = t;
                t.x = v0; t.y = v1;
                *(float2*)(vr_out + idx) = t;
                t.x = w0; t.y = w1;
                *(float2*)(wn_out + idx) = t;
            }
        }
    }
}

extern "C" void kernel_launch(void* const* d_in, const int* in_sizes, int n_in,
                              void* d_out, int out_size) {
    const float* x = (const float*)d_in[0];
    const float* W = (const float*)d_in[1];
    const float* gNa = (const float*)d_in[2];
    const float* gK = (const float*)d_in[3];
    const float* gL = (const float*)d_in[4];
    float* out = (float*)d_out;

    const int M = in_sizes[0] / KDIM;  // 16384

    cudaFuncSetAttribute(CSnT_snn_kernel,
                         cudaFuncAttributeMaxDynamicSharedMemorySize, SMEM_BYTES);

    CSnT_cvt_kernel<<<1024, 256>>>(x, W);

    dim3 grid(NDIM / BN, M / BM);  // (4, 128)
    CSnT_snn_kernel<<<grid, 256, SMEM_BYTES>>>(gNa, gK, gL, out, M);
}